// round 16
// baseline (speedup 1.0000x reference)
#include <cuda_runtime.h>
#include <cstdint>

#define NN 50000
#define EE 800000
#define GG 50

// ---------------- edge kernel geometry (warp-closed, 15 warps) ----------------
#define W1S 168
#define W2S 72
#define MHSH 168          // M row stride in halves (336B)
#define MWB 10752         // M bytes per warp (hi 5376 + lo 5376)

#define OFF_W1H 0
#define OFF_W1L 21504
#define OFF_W2H 43008
#define OFF_W2L 52224
#define OFF_B1  61440
#define OFF_B2  61696
#define OFF_M   61952     // 15 * 10752 = 161280
#define EDGE_SMEM 223232

// ---------------- fused gates+lstm geometry (7 pairs, pipelined) ----------------
#define WFS 136
#define OFF_WFH 0
#define OFF_WFL 69632
#define OFF_BS  139264
#define OFF_XAH 140288    // 7 * 4352 = 30464
#define OFF_XAL 170752    // 30464
#define GATES_SMEM 201216
#define XAPAIRB 4352

typedef unsigned long long ull;

// -------- persistent device scratch --------
__device__ float g_x[NN * 64];
__device__ float g_c[NN * 64];
__device__ float g_a[NN * 64];
__device__ int   g_idx64;

// -------- packed f32x2 helpers (readout) --------
__device__ __forceinline__ ull dup2(float x) {
    ull r; asm("mov.b64 %0, {%1,%1};" : "=l"(r) : "f"(x)); return r;
}
__device__ __forceinline__ ull pack2f(float x, float y) {
    ull r; asm("mov.b64 %0, {%1,%2};" : "=l"(r) : "f"(x), "f"(y)); return r;
}
__device__ __forceinline__ void fma2(ull& d, ull a, ull b) {
    asm("fma.rn.f32x2 %0, %1, %2, %0;" : "+l"(d) : "l"(a), "l"(b));
}
__device__ __forceinline__ float2 unpack2(ull v) {
    float lo, hi; asm("mov.b64 {%0,%1}, %2;" : "=f"(lo), "=f"(hi) : "l"(v));
    return make_float2(lo, hi);
}

__device__ __forceinline__ float sigf(float x) { return 1.f / (1.f + __expf(-x)); }
__device__ __forceinline__ float tanh_f(float x) {
    float t = __expf(-2.f * fabsf(x));
    float r = (1.f - t) / (1.f + t);
    return copysignf(r, x);
}

__device__ __forceinline__ uint32_t smem_u32(const void* p) {
    uint32_t a;
    asm("{ .reg .u64 t; cvta.to.shared.u64 t, %1; cvt.u32.u64 %0, t; }" : "=r"(a) : "l"(p));
    return a;
}

// -------- bf16 split helpers --------
__device__ __forceinline__ void bsplit2(float v0, float v1, uint32_t& h, uint32_t& l) {
    asm("cvt.rn.bf16x2.f32 %0, %2, %1;" : "=r"(h) : "f"(v0), "f"(v1));
    float r0 = v0 - __uint_as_float(h << 16);
    float r1 = v1 - __uint_as_float(h & 0xffff0000u);
    asm("cvt.rn.bf16x2.f32 %0, %2, %1;" : "=r"(l) : "f"(r0), "f"(r1));
}
__device__ __forceinline__ void bsplit1(float v, uint16_t& h, uint16_t& l) {
    uint32_t p;
    asm("cvt.rn.bf16x2.f32 %0, %1, %1;" : "=r"(p) : "f"(v));
    h = (uint16_t)(p & 0xffffu);
    float r = v - __uint_as_float(p << 16);
    asm("cvt.rn.bf16x2.f32 %0, %1, %1;" : "=r"(p) : "f"(r));
    l = (uint16_t)(p & 0xffffu);
}

__device__ __forceinline__ void mma16816(float* c, const uint32_t* A, uint32_t b0, uint32_t b1) {
    asm volatile("mma.sync.aligned.m16n8k16.row.col.f32.bf16.bf16.f32 "
                 "{%0,%1,%2,%3}, {%4,%5,%6,%7}, {%8,%9}, {%0,%1,%2,%3};"
                 : "+f"(c[0]), "+f"(c[1]), "+f"(c[2]), "+f"(c[3])
                 : "r"(A[0]), "r"(A[1]), "r"(A[2]), "r"(A[3]), "r"(b0), "r"(b1));
}

__device__ __forceinline__ void ldm4(uint32_t addr, uint32_t& r0, uint32_t& r1,
                                     uint32_t& r2, uint32_t& r3) {
    asm volatile("ldmatrix.sync.aligned.m8n8.x4.shared.b16 {%0,%1,%2,%3}, [%4];"
                 : "=r"(r0), "=r"(r1), "=r"(r2), "=r"(r3) : "r"(addr));
}

#define BARP(id) asm volatile("bar.sync %0, %1;" :: "r"(id), "r"(64) : "memory")

// -------- parallel dtype detection --------
__global__ void detect_kernel(const int* __restrict__ raw) {
    __shared__ int cnt;
    if (threadIdx.x == 0) cnt = 0;
    __syncthreads();
    int z = 0;
    for (int j = threadIdx.x; j < 1024; j += 256) z += (raw[2 * j + 1] == 0);
    #pragma unroll
    for (int o = 16; o > 0; o >>= 1) z += __shfl_xor_sync(0xffffffffu, z, o);
    if ((threadIdx.x & 31) == 0) atomicAdd(&cnt, z);
    __syncthreads();
    if (threadIdx.x == 0) g_idx64 = (cnt > 512) ? 1 : 0;
}

// -------- init --------
__global__ void init_kernel(const float4* __restrict__ x, float* __restrict__ out) {
    int i = blockIdx.x * blockDim.x + threadIdx.x;
    if (i < NN * 16) ((float4*)g_x)[i] = x[i];
    if (i < GG) out[i] = 0.f;
}
__global__ void zero_kernel() {
    int i = blockIdx.x * blockDim.x + threadIdx.x;
    if (i < NN * 16) {
        float4 z = make_float4(0.f, 0.f, 0.f, 0.f);
        ((float4*)g_c)[i] = z;
        ((float4*)g_a)[i] = z;
    }
}

// =====================================================================
// Edge MPN: WARP-CLOSED 16-edge tiles, software-pipelined, 480 threads
// (15 warps). GEMM2 A-frags in-register; direct red.v2 scatter.
// =====================================================================
__global__ __launch_bounds__(480, 1) void edge_kernel(
    const float* __restrict__ ea, const void* __restrict__ idx,
    const float* __restrict__ W1, const float* __restrict__ b1,
    const float* __restrict__ W2, const float* __restrict__ b2)
{
    extern __shared__ char sm[];
    uint16_t* w1h = (uint16_t*)(sm + OFF_W1H);
    uint16_t* w1l = (uint16_t*)(sm + OFF_W1L);
    uint16_t* w2h = (uint16_t*)(sm + OFF_W2H);
    uint16_t* w2l = (uint16_t*)(sm + OFF_W2L);
    float* b1s = (float*)(sm + OFF_B1);
    float* b2s = (float*)(sm + OFF_B2);

    const int tid = threadIdx.x;

    for (int i = tid; i < 10240; i += 480) {
        int k = i >> 6, n = i & 63;
        uint16_t h, l; bsplit1(W1[i], h, l);
        int off = n * W1S + k;
        w1h[off] = h; w1l[off] = l;
    }
    for (int i = tid; i < 4096; i += 480) {
        int k = i >> 6, n = i & 63;
        uint16_t h, l; bsplit1(W2[i], h, l);
        int off = n * W2S + k;
        w2h[off] = h; w2l[off] = l;
    }
    if (tid < 64) { b1s[tid] = b1[tid]; b2s[tid] = b2[tid]; }
    __syncthreads();

    const int is64 = g_idx64;
    const long long* i64 = (const long long*)idx;
    const int*       i32 = (const int*)idx;

    const int wid  = tid >> 5;
    const int lane = tid & 31;
    const int r    = lane >> 2;
    const int q    = lane & 3;
    const uint32_t sb = smem_u32(sm);

    uint16_t* mhB = (uint16_t*)(sm + OFF_M + wid * MWB);
    uint16_t* mlB = mhB + 2688;
    const uint32_t aMh = sb + OFF_M + wid * MWB
                       + (uint32_t)(lane & 15) * 336 + ((lane >> 4) << 4);
    const uint32_t aMl = aMh + 5376;

    const int gq   = lane >> 3;
    const int rowi = lane & 7;
    const int subn = ((gq >> 1) << 3) + rowi;
    const int koff = (gq & 1) << 3;
    uint32_t a1h[4], a1l[4], a2h[4], a2l[4];
    #pragma unroll
    for (int p = 0; p < 4; p++) {
        int n = p * 16 + subn;
        a1h[p] = sb + OFF_W1H + (uint32_t)(n * W1S + koff) * 2;
        a1l[p] = sb + OFF_W1L + (uint32_t)(n * W1S + koff) * 2;
        a2h[p] = sb + OFF_W2H + (uint32_t)(n * W2S + koff) * 2;
        a2l[p] = sb + OFF_W2L + (uint32_t)(n * W2S + koff) * 2;
    }

    const int gseg  = lane & 7;
    const int grow0 = lane >> 3;
    const int NT = EE / 16;
    const int stride = gridDim.x * 15;

    auto gather = [&](int g, int& mynv) {
        int eg16 = g * 16 + (lane & 15);
        mynv = is64 ? (int)i64[(lane < 16) ? (EE + eg16) : eg16]
                    : i32[(lane < 16) ? (EE + eg16) : eg16];
        #pragma unroll
        for (int i = 0; i < 4; i++) {
            int row = i * 4 + grow0;
            int nd = __shfl_sync(0xffffffffu, mynv, row);
            int ns = __shfl_sync(0xffffffffu, mynv, 16 + row);
            const float4* xrd = (const float4*)(g_x + (size_t)nd * 64);
            const float4* xrs = (const float4*)(g_x + (size_t)ns * 64);
            const float4* er  = ((const float4*)ea) + (size_t)(g * 16 + row) * 8;
            float4 fd0 = xrd[gseg];
            float4 fd1 = xrd[gseg + 8];
            float4 fs0 = xrs[gseg];
            float4 fs1 = xrs[gseg + 8];
            float4 fe  = __ldcs(er + gseg);

            uint16_t* mh = mhB + row * MHSH + gseg * 4;
            uint16_t* ml = mlB + row * MHSH + gseg * 4;
            uint32_t h0, l0, h1, l1, h2, l2, h3, l3;
            bsplit2(fd0.x, fd0.y, h0, l0); bsplit2(fd0.z, fd0.w, h1, l1);
            bsplit2(fd1.x, fd1.y, h2, l2); bsplit2(fd1.z, fd1.w, h3, l3);
            *(uint2*)mh        = make_uint2(h0, h1);
            *(uint2*)(mh + 32) = make_uint2(h2, h3);
            *(uint2*)ml        = make_uint2(l0, l1);
            *(uint2*)(ml + 32) = make_uint2(l2, l3);
            bsplit2(fs0.x, fs0.y, h0, l0); bsplit2(fs0.z, fs0.w, h1, l1);
            bsplit2(fs1.x, fs1.y, h2, l2); bsplit2(fs1.z, fs1.w, h3, l3);
            *(uint2*)(mh + 64) = make_uint2(h0, h1);
            *(uint2*)(mh + 96) = make_uint2(h2, h3);
            *(uint2*)(ml + 64) = make_uint2(l0, l1);
            *(uint2*)(ml + 96) = make_uint2(l2, l3);
            bsplit2(fe.x, fe.y, h0, l0); bsplit2(fe.z, fe.w, h1, l1);
            *(uint2*)(mh + 128) = make_uint2(h0, h1);
            *(uint2*)(ml + 128) = make_uint2(l0, l1);
        }
    };

    int grp = blockIdx.x * 15 + wid;
    int myn = 0;
    if (grp < NT) gather(grp, myn);

    while (grp < NT) {
        int nxt = grp + stride;
        __syncwarp();

        float acc[8][4];
        #pragma unroll
        for (int nt = 0; nt < 8; nt++) {
            float bb0 = b1s[nt * 8 + 2 * q], bb1 = b1s[nt * 8 + 2 * q + 1];
            acc[nt][0] = bb0; acc[nt][1] = bb1; acc[nt][2] = bb0; acc[nt][3] = bb1;
        }
        #pragma unroll
        for (int kt = 0; kt < 160; kt += 16) {
            uint32_t Ah[4], Al[4];
            ldm4(aMh + kt * 2, Ah[0], Ah[1], Ah[2], Ah[3]);
            ldm4(aMl + kt * 2, Al[0], Al[1], Al[2], Al[3]);
            #pragma unroll
            for (int p = 0; p < 4; p++) {
                uint32_t bh0, bh1, bh2, bh3, bl0, bl1, bl2, bl3;
                ldm4(a1h[p] + kt * 2, bh0, bh1, bh2, bh3);
                ldm4(a1l[p] + kt * 2, bl0, bl1, bl2, bl3);
                mma16816(acc[2 * p],     Ah, bh0, bh1);
                mma16816(acc[2 * p],     Al, bh0, bh1);
                mma16816(acc[2 * p],     Ah, bl0, bl1);
                mma16816(acc[2 * p + 1], Ah, bh2, bh3);
                mma16816(acc[2 * p + 1], Al, bh2, bh3);
                mma16816(acc[2 * p + 1], Ah, bl2, bl3);
            }
        }

        uint32_t Ah2[4][4], Al2[4][4];
        #pragma unroll
        for (int kt2 = 0; kt2 < 4; kt2++) {
            float* a0 = acc[2 * kt2];
            float* a1 = acc[2 * kt2 + 1];
            bsplit2(fmaxf(a0[0], 0.f), fmaxf(a0[1], 0.f), Ah2[kt2][0], Al2[kt2][0]);
            bsplit2(fmaxf(a0[2], 0.f), fmaxf(a0[3], 0.f), Ah2[kt2][1], Al2[kt2][1]);
            bsplit2(fmaxf(a1[0], 0.f), fmaxf(a1[1], 0.f), Ah2[kt2][2], Al2[kt2][2]);
            bsplit2(fmaxf(a1[2], 0.f), fmaxf(a1[3], 0.f), Ah2[kt2][3], Al2[kt2][3]);
        }
        __syncwarp();

        int myn2 = 0;
        if (nxt < NT) gather(nxt, myn2);

        float acc2[8][4];
        #pragma unroll
        for (int nt = 0; nt < 8; nt++) {
            float bb0 = b2s[nt * 8 + 2 * q], bb1 = b2s[nt * 8 + 2 * q + 1];
            acc2[nt][0] = bb0; acc2[nt][1] = bb1; acc2[nt][2] = bb0; acc2[nt][3] = bb1;
        }
        #pragma unroll
        for (int kt2 = 0; kt2 < 4; kt2++) {
            #pragma unroll
            for (int p = 0; p < 4; p++) {
                uint32_t bh0, bh1, bh2, bh3, bl0, bl1, bl2, bl3;
                ldm4(a2h[p] + kt2 * 32, bh0, bh1, bh2, bh3);
                ldm4(a2l[p] + kt2 * 32, bl0, bl1, bl2, bl3);
                mma16816(acc2[2 * p],     Ah2[kt2], bh0, bh1);
                mma16816(acc2[2 * p],     Al2[kt2], bh0, bh1);
                mma16816(acc2[2 * p],     Ah2[kt2], bl0, bl1);
                mma16816(acc2[2 * p + 1], Ah2[kt2], bh2, bh3);
                mma16816(acc2[2 * p + 1], Al2[kt2], bh2, bh3);
                mma16816(acc2[2 * p + 1], Ah2[kt2], bl2, bl3);
            }
        }

        int n0 = __shfl_sync(0xffffffffu, myn, r);
        int n1 = __shfl_sync(0xffffffffu, myn, r + 8);
        #pragma unroll
        for (int nt = 0; nt < 8; nt++) {
            int c0 = nt * 8 + 2 * q;
            float* dp0 = g_a + (size_t)n0 * 64 + c0;
            float* dp1 = g_a + (size_t)n1 * 64 + c0;
            asm volatile("red.global.add.v2.f32 [%0], {%1,%2};"
                         :: "l"(dp0), "f"(acc2[nt][0]), "f"(acc2[nt][1]) : "memory");
            asm volatile("red.global.add.v2.f32 [%0], {%1,%2};"
                         :: "l"(dp1), "f"(acc2[nt][2]), "f"(acc2[nt][3]) : "memory");
        }

        myn = myn2;
        grp = nxt;
    }
}

// =====================================================================
// FUSED gates GEMM + LSTM cell — PIPELINED: next tile's gather LDGs
// issue before the GEMM (prefetch regs die before acc peak). 448 thr.
// =====================================================================
__global__ __launch_bounds__(448, 1) void gates_lstm_kernel(
    const float* __restrict__ Wih, const float* __restrict__ Whh,
    const float* __restrict__ bih, const float* __restrict__ bhh)
{
    extern __shared__ char sm[];
    uint16_t* wfh = (uint16_t*)(sm + OFF_WFH);
    uint16_t* wfl = (uint16_t*)(sm + OFF_WFL);
    float* bs = (float*)(sm + OFF_BS);

    const int tid = threadIdx.x;

    for (int i = tid; i < 32768; i += 448) {
        int k = i >> 8, n = i & 255;
        float w = (k < 64) ? Wih[k * 256 + n] : Whh[(k - 64) * 256 + n];
        uint16_t h, l; bsplit1(w, h, l);
        int off = n * WFS + k;
        wfh[off] = h; wfl[off] = l;
    }
    for (int i = tid; i < 256; i += 448) bs[i] = bih[i] + bhh[i];
    __syncthreads();

    const int wid  = tid >> 5;
    const int lane = tid & 31;
    const int pair = wid >> 1;
    const int w01  = wid & 1;
    const int r    = lane >> 2;
    const int q    = lane & 3;
    const int d0   = w01 * 32;
    const int barid = pair + 1;
    const uint32_t sb = smem_u32(sm);

    const uint32_t aoff = (uint32_t)(lane & 15) * (WFS * 2) + ((lane >> 4) << 4);
    const uint32_t aXh = sb + OFF_XAH + pair * XAPAIRB + aoff;
    const uint32_t aXl = sb + OFF_XAL + pair * XAPAIRB + aoff;
    const int gq   = lane >> 3;
    const int rowi = lane & 7;
    const int subn = ((gq >> 1) << 3) + rowi;
    const int koff = (gq & 1) << 3;
    const uint32_t bBh = sb + OFF_WFH + (uint32_t)((d0 + subn) * WFS + koff) * 2;
    const uint32_t bBl = sb + OFF_WFL + (uint32_t)((d0 + subn) * WFS + koff) * 2;

    const int gseg  = lane & 7;
    const int grow0 = lane >> 3;
    uint16_t* XHp = (uint16_t*)(sm + OFF_XAH) + pair * (XAPAIRB / 2);
    uint16_t* XLp = (uint16_t*)(sm + OFF_XAL) + pair * (XAPAIRB / 2);

    const int GT = NN / 16;
    const int gstride = gridDim.x * 7;
    const float* src = w01 ? g_a : g_x;

    auto loadg = [&](int g, float4* pf) {
        int nb2 = g * 16;
        #pragma unroll
        for (int i = 0; i < 4; i++) {
            int row = i * 4 + grow0;
            const float4* xr = (const float4*)(src + (size_t)(nb2 + row) * 64);
            pf[2 * i]     = xr[gseg];
            pf[2 * i + 1] = xr[gseg + 8];
        }
    };

    int grp = blockIdx.x * 7 + pair;
    float4 pf[8];
    if (grp < GT) loadg(grp, pf);

    while (grp < GT) {
        int nb = grp * 16;
        int nxt = grp + gstride;
        BARP(barid);   // previous tile's ldmatrix reads done

        // ---- split prefetched A -> XA smem ----
        #pragma unroll
        for (int i = 0; i < 4; i++) {
            int row = i * 4 + grow0;
            uint32_t h0, l0, h1, l1, h2, l2, h3, l3;
            float4 f0 = pf[2 * i], f1 = pf[2 * i + 1];
            bsplit2(f0.x, f0.y, h0, l0); bsplit2(f0.z, f0.w, h1, l1);
            bsplit2(f1.x, f1.y, h2, l2); bsplit2(f1.z, f1.w, h3, l3);
            uint16_t* mh = XHp + row * WFS + w01 * 64 + gseg * 4;
            uint16_t* ml = XLp + row * WFS + w01 * 64 + gseg * 4;
            *(uint2*)mh        = make_uint2(h0, h1);
            *(uint2*)(mh + 32) = make_uint2(h2, h3);
            *(uint2*)ml        = make_uint2(l0, l1);
            *(uint2*)(ml + 32) = make_uint2(l2, l3);
        }
        BARP(barid);   // XA complete

        // ---- PIPELINED: next tile's LDGs overlap the GEMM ----
        if (nxt < GT) loadg(nxt, pf);

        float acc[16][4];
        #pragma unroll
        for (int gi = 0; gi < 4; gi++)
            #pragma unroll
            for (int t = 0; t < 2; t++)
                #pragma unroll
                for (int s = 0; s < 2; s++) {
                    int c0 = 64 * gi + d0 + 16 * t + 8 * s + 2 * q;
                    float bb0 = bs[c0], bb1 = bs[c0 + 1];
                    float* a = acc[gi * 4 + t * 2 + s];
                    a[0] = bb0; a[1] = bb1; a[2] = bb0; a[3] = bb1;
                }
        #pragma unroll
        for (int kt = 0; kt < 128; kt += 16) {
            uint32_t Ah[4], Al[4];
            ldm4(aXh + kt * 2, Ah[0], Ah[1], Ah[2], Ah[3]);
            ldm4(aXl + kt * 2, Al[0], Al[1], Al[2], Al[3]);
            #pragma unroll
            for (int gi = 0; gi < 4; gi++) {
                #pragma unroll
                for (int t = 0; t < 2; t++) {
                    uint32_t boff = (uint32_t)((64 * gi + 16 * t) * WFS + kt) * 2;
                    uint32_t bh0, bh1, bh2, bh3, bl0, bl1, bl2, bl3;
                    ldm4(bBh + boff, bh0, bh1, bh2, bh3);
                    ldm4(bBl + boff, bl0, bl1, bl2, bl3);
                    float* a0 = acc[gi * 4 + t * 2];
                    float* a1 = acc[gi * 4 + t * 2 + 1];
                    mma16816(a0, Ah, bh0, bh1);
                    mma16816(a0, Al, bh0, bh1);
                    mma16816(a0, Ah, bl0, bl1);
                    mma16816(a1, Ah, bh2, bh3);
                    mma16816(a1, Al, bh2, bh3);
                    mma16816(a1, Ah, bl2, bl3);
                }
            }
        }

        #pragma unroll
        for (int t = 0; t < 2; t++) {
            #pragma unroll
            for (int s = 0; s < 2; s++) {
                int idx = t * 2 + s;
                int d = d0 + 16 * t + 8 * s + 2 * q;
                float* ai = acc[idx];
                float* af = acc[4 + idx];
                float* ag = acc[8 + idx];
                float* ao = acc[12 + idx];
                #pragma unroll
                for (int rr = 0; rr < 2; rr++) {
                    int node = nb + r + rr * 8;
                    float2* cp = (float2*)(g_c + (size_t)node * 64 + d);
                    float2 c = *cp;
                    float nc0 = sigf(af[2*rr]) * c.x + sigf(ai[2*rr]) * tanh_f(ag[2*rr]);
                    float nc1 = sigf(af[2*rr+1]) * c.y + sigf(ai[2*rr+1]) * tanh_f(ag[2*rr+1]);
                    *cp = make_float2(nc0, nc1);
                    float nh0 = sigf(ao[2*rr]) * tanh_f(nc0);
                    float nh1 = sigf(ao[2*rr+1]) * tanh_f(nc1);
                    *(float2*)(g_x + (size_t)node * 64 + d) = make_float2(nh0, nh1);
                    *(float2*)(g_a + (size_t)node * 64 + d) = make_float2(0.f, 0.f);
                }
            }
        }
        grp = nxt;
    }
}

// -------- readout --------
__global__ __launch_bounds__(256) void readout_kernel(
    const float* __restrict__ gmW, const float* __restrict__ gmb,
    const float* __restrict__ fmW, const float* __restrict__ fmb,
    float* __restrict__ out)
{
    extern __shared__ float smf[];
    float* Gs = smf;
    float* Fs = smf + 3200;
    float* Gb = smf + 6400;
    float* Fb = smf + 6450;
    int tid = threadIdx.x;
    for (int i = tid; i < 3200; i += 256) { Gs[i] = gmW[i]; Fs[i] = fmW[i]; }
    if (tid < GG) { Gb[tid] = gmb[tid]; Fb[tid] = fmb[tid]; }
    __syncthreads();

    int n = blockIdx.x * 256 + tid;
    bool valid = n < NN;
    float xr[64];
    if (valid) {
        const float4* xp = ((const float4*)g_x) + (size_t)n * 16;
        #pragma unroll
        for (int i = 0; i < 16; i++) {
            float4 v = xp[i];
            xr[4 * i] = v.x; xr[4 * i + 1] = v.y; xr[4 * i + 2] = v.z; xr[4 * i + 3] = v.w;
        }
    } else {
        #pragma unroll
        for (int i = 0; i < 64; i++) xr[i] = 0.f;
    }

    #pragma unroll 1
    for (int gp2 = 0; gp2 < 25; gp2++) {
        ull a1 = pack2f(Gb[2 * gp2], Gb[2 * gp2 + 1]);
        ull a2 = pack2f(Fb[2 * gp2], Fb[2 * gp2 + 1]);
        #pragma unroll
        for (int k = 0; k < 64; k++) {
            ull xd = dup2(xr[k]);
            fma2(a1, xd, *(const ull*)(Gs + k * 50 + 2 * gp2));
            fma2(a2, xd, *(const ull*)(Fs + k * 50 + 2 * gp2));
        }
        float2 s1 = unpack2(a1), s2 = unpack2(a2);
        float v0 = valid ? sigf(s1.x) * s2.x : 0.f;
        float v1 = valid ? sigf(s1.y) * s2.y : 0.f;
        #pragma unroll
        for (int o = 16; o > 0; o >>= 1) {
            v0 += __shfl_xor_sync(0xffffffffu, v0, o);
            v1 += __shfl_xor_sync(0xffffffffu, v1, o);
        }
        if ((tid & 31) == 0) {
            atomicAdd(&out[2 * gp2], v0);
            atomicAdd(&out[2 * gp2 + 1], v1);
        }
    }
}

// =====================================================================
extern "C" void kernel_launch(void* const* d_in, const int* in_sizes, int n_in,
                              void* d_out, int out_size)
{
    const float* x  = (const float*)d_in[0];
    const float* ea = (const float*)d_in[1];
    const void*  idx = d_in[2];
    const float* feW1[2] = {(const float*)d_in[3],  (const float*)d_in[11]};
    const float* feb1[2] = {(const float*)d_in[4],  (const float*)d_in[12]};
    const float* feW2[2] = {(const float*)d_in[5],  (const float*)d_in[13]};
    const float* feb2[2] = {(const float*)d_in[6],  (const float*)d_in[14]};
    const float* Wih[2]  = {(const float*)d_in[7],  (const float*)d_in[15]};
    const float* Whh[2]  = {(const float*)d_in[8],  (const float*)d_in[16]};
    const float* bih[2]  = {(const float*)d_in[9],  (const float*)d_in[17]};
    const float* bhh[2]  = {(const float*)d_in[10], (const float*)d_in[18]};
    float* out = (float*)d_out;

    cudaFuncSetAttribute(edge_kernel,       cudaFuncAttributeMaxDynamicSharedMemorySize, EDGE_SMEM);
    cudaFuncSetAttribute(gates_lstm_kernel, cudaFuncAttributeMaxDynamicSharedMemorySize, GATES_SMEM);
    cudaFuncSetAttribute(readout_kernel,    cudaFuncAttributeMaxDynamicSharedMemorySize, 26112);

    detect_kernel<<<1, 256>>>((const int*)idx);                          // 1
    init_kernel<<<(NN * 16 + 255) / 256, 256>>>((const float4*)x, out);  // 2
    zero_kernel<<<(NN * 16 + 255) / 256, 256>>>();                       // 3

    for (int s = 0; s < 2; s++) {
        edge_kernel<<<148, 480, EDGE_SMEM>>>(ea, idx, feW1[s], feb1[s], feW2[s], feb2[s]); // 4, 6 <- profiled
        gates_lstm_kernel<<<148, 448, GATES_SMEM>>>(Wih[s], Whh[s], bih[s], bhh[s]);       // 5, 7
    }

    readout_kernel<<<(NN + 255) / 256, 256, 26112>>>(
        (const float*)d_in[19], (const float*)d_in[20],
        (const float*)d_in[21], (const float*)d_in[22], out);            // 8
}

// round 17
// speedup vs baseline: 1.0472x; 1.0472x over previous
#include <cuda_runtime.h>
#include <cstdint>

#define NN 50000
#define EE 800000
#define GG 50

// ---------------- edge kernel geometry (warp-closed, 15 warps) ----------------
#define W1S 168
#define W2S 72
#define MHSH 168          // M row stride in halves (336B)
#define MWB 10752         // M bytes per warp (hi 5376 + lo 5376)

#define OFF_W1H 0
#define OFF_W1L 21504
#define OFF_W2H 43008
#define OFF_W2L 52224
#define OFF_B1  61440
#define OFF_B2  61696
#define OFF_M   61952     // 15 * 10752 = 161280
#define EDGE_SMEM 223232

// ---------------- fused gates+lstm geometry (8 pairs, round-10 proven) ----------------
#define WFS 136
#define OFF_WFH 0
#define OFF_WFL 69632
#define OFF_BS  139264
#define OFF_XAH 140288    // 8 * 4352 = 34816
#define OFF_XAL 175104
#define GATES_SMEM 209920
#define XAPAIRB 4352

typedef unsigned long long ull;

// -------- persistent device scratch --------
__device__ float g_x[NN * 64];
__device__ float g_c[NN * 64];
__device__ float g_a[NN * 64];
__device__ int   g_idx64;

// -------- packed f32x2 helpers (readout) --------
__device__ __forceinline__ ull dup2(float x) {
    ull r; asm("mov.b64 %0, {%1,%1};" : "=l"(r) : "f"(x)); return r;
}
__device__ __forceinline__ ull pack2f(float x, float y) {
    ull r; asm("mov.b64 %0, {%1,%2};" : "=l"(r) : "f"(x), "f"(y)); return r;
}
__device__ __forceinline__ void fma2(ull& d, ull a, ull b) {
    asm("fma.rn.f32x2 %0, %1, %2, %0;" : "+l"(d) : "l"(a), "l"(b));
}
__device__ __forceinline__ float2 unpack2(ull v) {
    float lo, hi; asm("mov.b64 {%0,%1}, %2;" : "=f"(lo), "=f"(hi) : "l"(v));
    return make_float2(lo, hi);
}

__device__ __forceinline__ float sigf(float x) { return 1.f / (1.f + __expf(-x)); }
__device__ __forceinline__ float tanh_f(float x) {
    float t = __expf(-2.f * fabsf(x));
    float r = (1.f - t) / (1.f + t);
    return copysignf(r, x);
}

__device__ __forceinline__ uint32_t smem_u32(const void* p) {
    uint32_t a;
    asm("{ .reg .u64 t; cvta.to.shared.u64 t, %1; cvt.u32.u64 %0, t; }" : "=r"(a) : "l"(p));
    return a;
}

// -------- bf16 split helpers --------
__device__ __forceinline__ void bsplit2(float v0, float v1, uint32_t& h, uint32_t& l) {
    asm("cvt.rn.bf16x2.f32 %0, %2, %1;" : "=r"(h) : "f"(v0), "f"(v1));
    float r0 = v0 - __uint_as_float(h << 16);
    float r1 = v1 - __uint_as_float(h & 0xffff0000u);
    asm("cvt.rn.bf16x2.f32 %0, %2, %1;" : "=r"(l) : "f"(r0), "f"(r1));
}
__device__ __forceinline__ void bsplit1(float v, uint16_t& h, uint16_t& l) {
    uint32_t p;
    asm("cvt.rn.bf16x2.f32 %0, %1, %1;" : "=r"(p) : "f"(v));
    h = (uint16_t)(p & 0xffffu);
    float r = v - __uint_as_float(p << 16);
    asm("cvt.rn.bf16x2.f32 %0, %1, %1;" : "=r"(p) : "f"(r));
    l = (uint16_t)(p & 0xffffu);
}

__device__ __forceinline__ void mma16816(float* c, const uint32_t* A, uint32_t b0, uint32_t b1) {
    asm volatile("mma.sync.aligned.m16n8k16.row.col.f32.bf16.bf16.f32 "
                 "{%0,%1,%2,%3}, {%4,%5,%6,%7}, {%8,%9}, {%0,%1,%2,%3};"
                 : "+f"(c[0]), "+f"(c[1]), "+f"(c[2]), "+f"(c[3])
                 : "r"(A[0]), "r"(A[1]), "r"(A[2]), "r"(A[3]), "r"(b0), "r"(b1));
}

__device__ __forceinline__ void ldm4(uint32_t addr, uint32_t& r0, uint32_t& r1,
                                     uint32_t& r2, uint32_t& r3) {
    asm volatile("ldmatrix.sync.aligned.m8n8.x4.shared.b16 {%0,%1,%2,%3}, [%4];"
                 : "=r"(r0), "=r"(r1), "=r"(r2), "=r"(r3) : "r"(addr));
}

#define BARP(id) asm volatile("bar.sync %0, %1;" :: "r"(id), "r"(64) : "memory")

// -------- parallel dtype detection --------
__global__ void detect_kernel(const int* __restrict__ raw) {
    __shared__ int cnt;
    if (threadIdx.x == 0) cnt = 0;
    __syncthreads();
    int z = 0;
    for (int j = threadIdx.x; j < 1024; j += 256) z += (raw[2 * j + 1] == 0);
    #pragma unroll
    for (int o = 16; o > 0; o >>= 1) z += __shfl_xor_sync(0xffffffffu, z, o);
    if ((threadIdx.x & 31) == 0) atomicAdd(&cnt, z);
    __syncthreads();
    if (threadIdx.x == 0) g_idx64 = (cnt > 512) ? 1 : 0;
}

// -------- init --------
__global__ void init_kernel(const float4* __restrict__ x, float* __restrict__ out) {
    int i = blockIdx.x * blockDim.x + threadIdx.x;
    if (i < NN * 16) ((float4*)g_x)[i] = x[i];
    if (i < GG) out[i] = 0.f;
}
__global__ void zero_kernel() {
    int i = blockIdx.x * blockDim.x + threadIdx.x;
    if (i < NN * 16) {
        float4 z = make_float4(0.f, 0.f, 0.f, 0.f);
        ((float4*)g_c)[i] = z;
        ((float4*)g_a)[i] = z;
    }
}

// =====================================================================
// Edge MPN (round-16, WIN): warp-closed 16-edge tiles, software-
// pipelined gather, 480 threads (15 warps), in-register GEMM2 A-frags.
// =====================================================================
__global__ __launch_bounds__(480, 1) void edge_kernel(
    const float* __restrict__ ea, const void* __restrict__ idx,
    const float* __restrict__ W1, const float* __restrict__ b1,
    const float* __restrict__ W2, const float* __restrict__ b2)
{
    extern __shared__ char sm[];
    uint16_t* w1h = (uint16_t*)(sm + OFF_W1H);
    uint16_t* w1l = (uint16_t*)(sm + OFF_W1L);
    uint16_t* w2h = (uint16_t*)(sm + OFF_W2H);
    uint16_t* w2l = (uint16_t*)(sm + OFF_W2L);
    float* b1s = (float*)(sm + OFF_B1);
    float* b2s = (float*)(sm + OFF_B2);

    const int tid = threadIdx.x;

    for (int i = tid; i < 10240; i += 480) {
        int k = i >> 6, n = i & 63;
        uint16_t h, l; bsplit1(W1[i], h, l);
        int off = n * W1S + k;
        w1h[off] = h; w1l[off] = l;
    }
    for (int i = tid; i < 4096; i += 480) {
        int k = i >> 6, n = i & 63;
        uint16_t h, l; bsplit1(W2[i], h, l);
        int off = n * W2S + k;
        w2h[off] = h; w2l[off] = l;
    }
    if (tid < 64) { b1s[tid] = b1[tid]; b2s[tid] = b2[tid]; }
    __syncthreads();

    const int is64 = g_idx64;
    const long long* i64 = (const long long*)idx;
    const int*       i32 = (const int*)idx;

    const int wid  = tid >> 5;
    const int lane = tid & 31;
    const int r    = lane >> 2;
    const int q    = lane & 3;
    const uint32_t sb = smem_u32(sm);

    uint16_t* mhB = (uint16_t*)(sm + OFF_M + wid * MWB);
    uint16_t* mlB = mhB + 2688;
    const uint32_t aMh = sb + OFF_M + wid * MWB
                       + (uint32_t)(lane & 15) * 336 + ((lane >> 4) << 4);
    const uint32_t aMl = aMh + 5376;

    const int gq   = lane >> 3;
    const int rowi = lane & 7;
    const int subn = ((gq >> 1) << 3) + rowi;
    const int koff = (gq & 1) << 3;
    uint32_t a1h[4], a1l[4], a2h[4], a2l[4];
    #pragma unroll
    for (int p = 0; p < 4; p++) {
        int n = p * 16 + subn;
        a1h[p] = sb + OFF_W1H + (uint32_t)(n * W1S + koff) * 2;
        a1l[p] = sb + OFF_W1L + (uint32_t)(n * W1S + koff) * 2;
        a2h[p] = sb + OFF_W2H + (uint32_t)(n * W2S + koff) * 2;
        a2l[p] = sb + OFF_W2L + (uint32_t)(n * W2S + koff) * 2;
    }

    const int gseg  = lane & 7;
    const int grow0 = lane >> 3;
    const int NT = EE / 16;
    const int stride = gridDim.x * 15;

    auto gather = [&](int g, int& mynv) {
        int eg16 = g * 16 + (lane & 15);
        mynv = is64 ? (int)i64[(lane < 16) ? (EE + eg16) : eg16]
                    : i32[(lane < 16) ? (EE + eg16) : eg16];
        #pragma unroll
        for (int i = 0; i < 4; i++) {
            int row = i * 4 + grow0;
            int nd = __shfl_sync(0xffffffffu, mynv, row);
            int ns = __shfl_sync(0xffffffffu, mynv, 16 + row);
            const float4* xrd = (const float4*)(g_x + (size_t)nd * 64);
            const float4* xrs = (const float4*)(g_x + (size_t)ns * 64);
            const float4* er  = ((const float4*)ea) + (size_t)(g * 16 + row) * 8;
            float4 fd0 = xrd[gseg];
            float4 fd1 = xrd[gseg + 8];
            float4 fs0 = xrs[gseg];
            float4 fs1 = xrs[gseg + 8];
            float4 fe  = __ldcs(er + gseg);

            uint16_t* mh = mhB + row * MHSH + gseg * 4;
            uint16_t* ml = mlB + row * MHSH + gseg * 4;
            uint32_t h0, l0, h1, l1, h2, l2, h3, l3;
            bsplit2(fd0.x, fd0.y, h0, l0); bsplit2(fd0.z, fd0.w, h1, l1);
            bsplit2(fd1.x, fd1.y, h2, l2); bsplit2(fd1.z, fd1.w, h3, l3);
            *(uint2*)mh        = make_uint2(h0, h1);
            *(uint2*)(mh + 32) = make_uint2(h2, h3);
            *(uint2*)ml        = make_uint2(l0, l1);
            *(uint2*)(ml + 32) = make_uint2(l2, l3);
            bsplit2(fs0.x, fs0.y, h0, l0); bsplit2(fs0.z, fs0.w, h1, l1);
            bsplit2(fs1.x, fs1.y, h2, l2); bsplit2(fs1.z, fs1.w, h3, l3);
            *(uint2*)(mh + 64) = make_uint2(h0, h1);
            *(uint2*)(mh + 96) = make_uint2(h2, h3);
            *(uint2*)(ml + 64) = make_uint2(l0, l1);
            *(uint2*)(ml + 96) = make_uint2(l2, l3);
            bsplit2(fe.x, fe.y, h0, l0); bsplit2(fe.z, fe.w, h1, l1);
            *(uint2*)(mh + 128) = make_uint2(h0, h1);
            *(uint2*)(ml + 128) = make_uint2(l0, l1);
        }
    };

    int grp = blockIdx.x * 15 + wid;
    int myn = 0;
    if (grp < NT) gather(grp, myn);

    while (grp < NT) {
        int nxt = grp + stride;
        __syncwarp();

        float acc[8][4];
        #pragma unroll
        for (int nt = 0; nt < 8; nt++) {
            float bb0 = b1s[nt * 8 + 2 * q], bb1 = b1s[nt * 8 + 2 * q + 1];
            acc[nt][0] = bb0; acc[nt][1] = bb1; acc[nt][2] = bb0; acc[nt][3] = bb1;
        }
        #pragma unroll
        for (int kt = 0; kt < 160; kt += 16) {
            uint32_t Ah[4], Al[4];
            ldm4(aMh + kt * 2, Ah[0], Ah[1], Ah[2], Ah[3]);
            ldm4(aMl + kt * 2, Al[0], Al[1], Al[2], Al[3]);
            #pragma unroll
            for (int p = 0; p < 4; p++) {
                uint32_t bh0, bh1, bh2, bh3, bl0, bl1, bl2, bl3;
                ldm4(a1h[p] + kt * 2, bh0, bh1, bh2, bh3);
                ldm4(a1l[p] + kt * 2, bl0, bl1, bl2, bl3);
                mma16816(acc[2 * p],     Ah, bh0, bh1);
                mma16816(acc[2 * p],     Al, bh0, bh1);
                mma16816(acc[2 * p],     Ah, bl0, bl1);
                mma16816(acc[2 * p + 1], Ah, bh2, bh3);
                mma16816(acc[2 * p + 1], Al, bh2, bh3);
                mma16816(acc[2 * p + 1], Ah, bl2, bl3);
            }
        }

        uint32_t Ah2[4][4], Al2[4][4];
        #pragma unroll
        for (int kt2 = 0; kt2 < 4; kt2++) {
            float* a0 = acc[2 * kt2];
            float* a1 = acc[2 * kt2 + 1];
            bsplit2(fmaxf(a0[0], 0.f), fmaxf(a0[1], 0.f), Ah2[kt2][0], Al2[kt2][0]);
            bsplit2(fmaxf(a0[2], 0.f), fmaxf(a0[3], 0.f), Ah2[kt2][1], Al2[kt2][1]);
            bsplit2(fmaxf(a1[0], 0.f), fmaxf(a1[1], 0.f), Ah2[kt2][2], Al2[kt2][2]);
            bsplit2(fmaxf(a1[2], 0.f), fmaxf(a1[3], 0.f), Ah2[kt2][3], Al2[kt2][3]);
        }
        __syncwarp();

        int myn2 = 0;
        if (nxt < NT) gather(nxt, myn2);

        float acc2[8][4];
        #pragma unroll
        for (int nt = 0; nt < 8; nt++) {
            float bb0 = b2s[nt * 8 + 2 * q], bb1 = b2s[nt * 8 + 2 * q + 1];
            acc2[nt][0] = bb0; acc2[nt][1] = bb1; acc2[nt][2] = bb0; acc2[nt][3] = bb1;
        }
        #pragma unroll
        for (int kt2 = 0; kt2 < 4; kt2++) {
            #pragma unroll
            for (int p = 0; p < 4; p++) {
                uint32_t bh0, bh1, bh2, bh3, bl0, bl1, bl2, bl3;
                ldm4(a2h[p] + kt2 * 32, bh0, bh1, bh2, bh3);
                ldm4(a2l[p] + kt2 * 32, bl0, bl1, bl2, bl3);
                mma16816(acc2[2 * p],     Ah2[kt2], bh0, bh1);
                mma16816(acc2[2 * p],     Al2[kt2], bh0, bh1);
                mma16816(acc2[2 * p],     Ah2[kt2], bl0, bl1);
                mma16816(acc2[2 * p + 1], Ah2[kt2], bh2, bh3);
                mma16816(acc2[2 * p + 1], Al2[kt2], bh2, bh3);
                mma16816(acc2[2 * p + 1], Ah2[kt2], bl2, bl3);
            }
        }

        int n0 = __shfl_sync(0xffffffffu, myn, r);
        int n1 = __shfl_sync(0xffffffffu, myn, r + 8);
        #pragma unroll
        for (int nt = 0; nt < 8; nt++) {
            int c0 = nt * 8 + 2 * q;
            float* dp0 = g_a + (size_t)n0 * 64 + c0;
            float* dp1 = g_a + (size_t)n1 * 64 + c0;
            asm volatile("red.global.add.v2.f32 [%0], {%1,%2};"
                         :: "l"(dp0), "f"(acc2[nt][0]), "f"(acc2[nt][1]) : "memory");
            asm volatile("red.global.add.v2.f32 [%0], {%1,%2};"
                         :: "l"(dp1), "f"(acc2[nt][2]), "f"(acc2[nt][3]) : "memory");
        }

        myn = myn2;
        grp = nxt;
    }
}

// =====================================================================
// FUSED gates GEMM + LSTM cell — round-10 proven version (512 thr, no
// prefetch): 62 us/launch.
// =====================================================================
__global__ __launch_bounds__(512, 1) void gates_lstm_kernel(
    const float* __restrict__ Wih, const float* __restrict__ Whh,
    const float* __restrict__ bih, const float* __restrict__ bhh)
{
    extern __shared__ char sm[];
    uint16_t* wfh = (uint16_t*)(sm + OFF_WFH);
    uint16_t* wfl = (uint16_t*)(sm + OFF_WFL);
    float* bs = (float*)(sm + OFF_BS);

    const int tid = threadIdx.x;

    for (int i = tid; i < 32768; i += 512) {
        int k = i >> 8, n = i & 255;
        float w = (k < 64) ? Wih[k * 256 + n] : Whh[(k - 64) * 256 + n];
        uint16_t h, l; bsplit1(w, h, l);
        int off = n * WFS + k;
        wfh[off] = h; wfl[off] = l;
    }
    if (tid < 256) bs[tid] = bih[tid] + bhh[tid];
    __syncthreads();

    const int wid  = tid >> 5;
    const int lane = tid & 31;
    const int pair = wid >> 1;
    const int w01  = wid & 1;
    const int r    = lane >> 2;
    const int q    = lane & 3;
    const int d0   = w01 * 32;
    const int barid = pair + 1;
    const uint32_t sb = smem_u32(sm);

    const uint32_t aoff = (uint32_t)(lane & 15) * (WFS * 2) + ((lane >> 4) << 4);
    const uint32_t aXh = sb + OFF_XAH + pair * XAPAIRB + aoff;
    const uint32_t aXl = sb + OFF_XAL + pair * XAPAIRB + aoff;
    const int gq   = lane >> 3;
    const int rowi = lane & 7;
    const int subn = ((gq >> 1) << 3) + rowi;
    const int koff = (gq & 1) << 3;
    const uint32_t bBh = sb + OFF_WFH + (uint32_t)((d0 + subn) * WFS + koff) * 2;
    const uint32_t bBl = sb + OFF_WFL + (uint32_t)((d0 + subn) * WFS + koff) * 2;

    const int gseg  = lane & 7;
    const int grow0 = lane >> 3;
    uint16_t* XHp = (uint16_t*)(sm + OFF_XAH) + pair * (XAPAIRB / 2);
    uint16_t* XLp = (uint16_t*)(sm + OFF_XAL) + pair * (XAPAIRB / 2);

    for (int grp = blockIdx.x * 8 + pair; grp < NN / 16; grp += gridDim.x * 8) {
        int nb = grp * 16;
        BARP(barid);

        {
            const float* src = w01 ? g_a : g_x;
            #pragma unroll
            for (int i = 0; i < 4; i++) {
                int row = i * 4 + grow0;
                const float4* xr = (const float4*)(src + (size_t)(nb + row) * 64);
                float4 f0 = xr[gseg];
                float4 f1 = xr[gseg + 8];
                uint32_t h0, l0, h1, l1, h2, l2, h3, l3;
                bsplit2(f0.x, f0.y, h0, l0); bsplit2(f0.z, f0.w, h1, l1);
                bsplit2(f1.x, f1.y, h2, l2); bsplit2(f1.z, f1.w, h3, l3);
                uint16_t* mh = XHp + row * WFS + w01 * 64 + gseg * 4;
                uint16_t* ml = XLp + row * WFS + w01 * 64 + gseg * 4;
                *(uint2*)mh        = make_uint2(h0, h1);
                *(uint2*)(mh + 32) = make_uint2(h2, h3);
                *(uint2*)ml        = make_uint2(l0, l1);
                *(uint2*)(ml + 32) = make_uint2(l2, l3);
            }
        }
        BARP(barid);

        float acc[16][4];
        #pragma unroll
        for (int gi = 0; gi < 4; gi++)
            #pragma unroll
            for (int t = 0; t < 2; t++)
                #pragma unroll
                for (int s = 0; s < 2; s++) {
                    int c0 = 64 * gi + d0 + 16 * t + 8 * s + 2 * q;
                    float bb0 = bs[c0], bb1 = bs[c0 + 1];
                    float* a = acc[gi * 4 + t * 2 + s];
                    a[0] = bb0; a[1] = bb1; a[2] = bb0; a[3] = bb1;
                }
        #pragma unroll
        for (int kt = 0; kt < 128; kt += 16) {
            uint32_t Ah[4], Al[4];
            ldm4(aXh + kt * 2, Ah[0], Ah[1], Ah[2], Ah[3]);
            ldm4(aXl + kt * 2, Al[0], Al[1], Al[2], Al[3]);
            #pragma unroll
            for (int gi = 0; gi < 4; gi++) {
                #pragma unroll
                for (int t = 0; t < 2; t++) {
                    uint32_t boff = (uint32_t)((64 * gi + 16 * t) * WFS + kt) * 2;
                    uint32_t bh0, bh1, bh2, bh3, bl0, bl1, bl2, bl3;
                    ldm4(bBh + boff, bh0, bh1, bh2, bh3);
                    ldm4(bBl + boff, bl0, bl1, bl2, bl3);
                    float* a0 = acc[gi * 4 + t * 2];
                    float* a1 = acc[gi * 4 + t * 2 + 1];
                    mma16816(a0, Ah, bh0, bh1);
                    mma16816(a0, Al, bh0, bh1);
                    mma16816(a0, Ah, bl0, bl1);
                    mma16816(a1, Ah, bh2, bh3);
                    mma16816(a1, Al, bh2, bh3);
                    mma16816(a1, Ah, bl2, bl3);
                }
            }
        }

        #pragma unroll
        for (int t = 0; t < 2; t++) {
            #pragma unroll
            for (int s = 0; s < 2; s++) {
                int idx = t * 2 + s;
                int d = d0 + 16 * t + 8 * s + 2 * q;
                float* ai = acc[idx];
                float* af = acc[4 + idx];
                float* ag = acc[8 + idx];
                float* ao = acc[12 + idx];
                #pragma unroll
                for (int rr = 0; rr < 2; rr++) {
                    int node = nb + r + rr * 8;
                    float2* cp = (float2*)(g_c + (size_t)node * 64 + d);
                    float2 c = *cp;
                    float nc0 = sigf(af[2*rr]) * c.x + sigf(ai[2*rr]) * tanh_f(ag[2*rr]);
                    float nc1 = sigf(af[2*rr+1]) * c.y + sigf(ai[2*rr+1]) * tanh_f(ag[2*rr+1]);
                    *cp = make_float2(nc0, nc1);
                    float nh0 = sigf(ao[2*rr]) * tanh_f(nc0);
                    float nh1 = sigf(ao[2*rr+1]) * tanh_f(nc1);
                    *(float2*)(g_x + (size_t)node * 64 + d) = make_float2(nh0, nh1);
                    *(float2*)(g_a + (size_t)node * 64 + d) = make_float2(0.f, 0.f);
                }
            }
        }
    }
}

// -------- readout --------
__global__ __launch_bounds__(256) void readout_kernel(
    const float* __restrict__ gmW, const float* __restrict__ gmb,
    const float* __restrict__ fmW, const float* __restrict__ fmb,
    float* __restrict__ out)
{
    extern __shared__ float smf[];
    float* Gs = smf;
    float* Fs = smf + 3200;
    float* Gb = smf + 6400;
    float* Fb = smf + 6450;
    int tid = threadIdx.x;
    for (int i = tid; i < 3200; i += 256) { Gs[i] = gmW[i]; Fs[i] = fmW[i]; }
    if (tid < GG) { Gb[tid] = gmb[tid]; Fb[tid] = fmb[tid]; }
    __syncthreads();

    int n = blockIdx.x * 256 + tid;
    bool valid = n < NN;
    float xr[64];
    if (valid) {
        const float4* xp = ((const float4*)g_x) + (size_t)n * 16;
        #pragma unroll
        for (int i = 0; i < 16; i++) {
            float4 v = xp[i];
            xr[4 * i] = v.x; xr[4 * i + 1] = v.y; xr[4 * i + 2] = v.z; xr[4 * i + 3] = v.w;
        }
    } else {
        #pragma unroll
        for (int i = 0; i < 64; i++) xr[i] = 0.f;
    }

    #pragma unroll 1
    for (int gp2 = 0; gp2 < 25; gp2++) {
        ull a1 = pack2f(Gb[2 * gp2], Gb[2 * gp2 + 1]);
        ull a2 = pack2f(Fb[2 * gp2], Fb[2 * gp2 + 1]);
        #pragma unroll
        for (int k = 0; k < 64; k++) {
            ull xd = dup2(xr[k]);
            fma2(a1, xd, *(const ull*)(Gs + k * 50 + 2 * gp2));
            fma2(a2, xd, *(const ull*)(Fs + k * 50 + 2 * gp2));
        }
        float2 s1 = unpack2(a1), s2 = unpack2(a2);
        float v0 = valid ? sigf(s1.x) * s2.x : 0.f;
        float v1 = valid ? sigf(s1.y) * s2.y : 0.f;
        #pragma unroll
        for (int o = 16; o > 0; o >>= 1) {
            v0 += __shfl_xor_sync(0xffffffffu, v0, o);
            v1 += __shfl_xor_sync(0xffffffffu, v1, o);
        }
        if ((tid & 31) == 0) {
            atomicAdd(&out[2 * gp2], v0);
            atomicAdd(&out[2 * gp2 + 1], v1);
        }
    }
}

// =====================================================================
extern "C" void kernel_launch(void* const* d_in, const int* in_sizes, int n_in,
                              void* d_out, int out_size)
{
    const float* x  = (const float*)d_in[0];
    const float* ea = (const float*)d_in[1];
    const void*  idx = d_in[2];
    const float* feW1[2] = {(const float*)d_in[3],  (const float*)d_in[11]};
    const float* feb1[2] = {(const float*)d_in[4],  (const float*)d_in[12]};
    const float* feW2[2] = {(const float*)d_in[5],  (const float*)d_in[13]};
    const float* feb2[2] = {(const float*)d_in[6],  (const float*)d_in[14]};
    const float* Wih[2]  = {(const float*)d_in[7],  (const float*)d_in[15]};
    const float* Whh[2]  = {(const float*)d_in[8],  (const float*)d_in[16]};
    const float* bih[2]  = {(const float*)d_in[9],  (const float*)d_in[17]};
    const float* bhh[2]  = {(const float*)d_in[10], (const float*)d_in[18]};
    float* out = (float*)d_out;

    cudaFuncSetAttribute(edge_kernel,       cudaFuncAttributeMaxDynamicSharedMemorySize, EDGE_SMEM);
    cudaFuncSetAttribute(gates_lstm_kernel, cudaFuncAttributeMaxDynamicSharedMemorySize, GATES_SMEM);
    cudaFuncSetAttribute(readout_kernel,    cudaFuncAttributeMaxDynamicSharedMemorySize, 26112);

    detect_kernel<<<1, 256>>>((const int*)idx);                          // 1
    init_kernel<<<(NN * 16 + 255) / 256, 256>>>((const float4*)x, out);  // 2
    zero_kernel<<<(NN * 16 + 255) / 256, 256>>>();                       // 3

    for (int s = 0; s < 2; s++) {
        edge_kernel<<<148, 480, EDGE_SMEM>>>(ea, idx, feW1[s], feb1[s], feW2[s], feb2[s]); // 4, 6 <- profiled
        gates_lstm_kernel<<<148, 512, GATES_SMEM>>>(Wih[s], Whh[s], bih[s], bhh[s]);       // 5, 7
    }

    readout_kernel<<<(NN + 255) / 256, 256, 26112>>>(
        (const float*)d_in[19], (const float*)d_in[20],
        (const float*)d_in[21], (const float*)d_in[22], out);            // 8
}